// round 6
// baseline (speedup 1.0000x reference)
#include <cuda_runtime.h>
#include <cuda_bf16.h>
#include <math.h>
#include <stdint.h>

#define S_DIM 16
#define B_DIM 512
#define H_DIM 2048
#define EPS 1e-8f

// ---------------------------------------------------------------------------
// Device scratch
// ---------------------------------------------------------------------------
__device__ __align__(16) __nv_bfloat16 g_Ahi[B_DIM * H_DIM];
__device__ __align__(16) __nv_bfloat16 g_Alo[B_DIM * H_DIM];

// ---------------------------------------------------------------------------
// PTX helpers (sm_80/90 baseline only — harness PTX target is sm_103, no 'a')
// ---------------------------------------------------------------------------
__device__ __forceinline__ uint32_t smem_u32(const void* p) {
    uint32_t r;
    asm("{ .reg .u64 t; cvta.to.shared.u64 t, %1; cvt.u32.u64 %0, t; }"
        : "=r"(r) : "l"(p));
    return r;
}
__device__ __forceinline__ void cpa16(uint32_t dst, const void* src) {
    asm volatile("cp.async.cg.shared.global [%0], [%1], 16;" :: "r"(dst), "l"(src));
}
#define CP_COMMIT() asm volatile("cp.async.commit_group;" ::: "memory")
#define CP_WAIT2()  asm volatile("cp.async.wait_group 2;" ::: "memory")

__device__ __forceinline__ void ldsm4(uint32_t* r, uint32_t addr) {
    asm volatile("ldmatrix.sync.aligned.m8n8.x4.shared.b16 {%0,%1,%2,%3}, [%4];"
                 : "=r"(r[0]), "=r"(r[1]), "=r"(r[2]), "=r"(r[3]) : "r"(addr));
}
__device__ __forceinline__ void mma16816(float* d, const uint32_t* a,
                                         uint32_t b0, uint32_t b1) {
    asm volatile(
        "mma.sync.aligned.m16n8k16.row.col.f32.bf16.bf16.f32 "
        "{%0,%1,%2,%3}, {%4,%5,%6,%7}, {%8,%9}, {%0,%1,%2,%3};"
        : "+f"(d[0]), "+f"(d[1]), "+f"(d[2]), "+f"(d[3])
        : "r"(a[0]), "r"(a[1]), "r"(a[2]), "r"(a[3]), "r"(b0), "r"(b1));
}
__device__ __forceinline__ float dot4(float4 a, float4 b) {
    return a.x * b.x + a.y * b.y + a.z * b.z + a.w * b.w;
}
// fp32 pair -> bf16 hi pair + bf16 lo pair (packed as u32)
__device__ __forceinline__ void split2(float x, float y, uint32_t& h, uint32_t& l) {
    __nv_bfloat162 hh = __floats2bfloat162_rn(x, y);
    float hx = __bfloat162float(__low2bfloat16(hh));
    float hy = __bfloat162float(__high2bfloat16(hh));
    __nv_bfloat162 ll = __floats2bfloat162_rn(x - hx, y - hy);
    h = *reinterpret_cast<uint32_t*>(&hh);
    l = *reinterpret_cast<uint32_t*>(&ll);
}

// ---------------------------------------------------------------------------
// Kernel 1 (fused): norms + sims + weightedRep -> bf16 hi/lo
// One CTA per b, 512 threads (one float4 slot per thread).
// enhanced[.,b,.] staged in 128KB smem, read from HBM ONCE.
// ---------------------------------------------------------------------------
#define FUSED_SMEM (S_DIM * (H_DIM / 4) * 16)   // 131072 B

__global__ void __launch_bounds__(512, 1)
fused_prep(const float* __restrict__ og, const float* __restrict__ enh) {
    extern __shared__ float4 se[];               // [S_DIM][H_DIM/4]
    __shared__ float red_d[S_DIM][16], red_e[S_DIM][16], red_o[16];
    __shared__ float sh_sims[S_DIM];

    const int b = blockIdx.x;
    const int tid = threadIdx.x;                 // 0..511 == float4 slot
    const int wid = tid >> 5, lid = tid & 31;

    const float4* og4 = reinterpret_cast<const float4*>(og) + (size_t)b * (H_DIM / 4);
    const float4 ogv = og4[tid];
    float o2 = dot4(ogv, ogv);

    const float4* e4 = reinterpret_cast<const float4*>(enh);
    float dots[S_DIM], e2s[S_DIM];
    #pragma unroll
    for (int s = 0; s < S_DIM; s++) {
        const size_t base = ((size_t)s * B_DIM + b) * (H_DIM / 4);
        float4 v = e4[base + tid];
        se[s * (H_DIM / 4) + tid] = v;
        dots[s] = dot4(v, ogv);
        e2s[s]  = dot4(v, v);
    }

    #pragma unroll
    for (int o = 16; o; o >>= 1) {
        o2 += __shfl_xor_sync(0xffffffffu, o2, o);
        #pragma unroll
        for (int s = 0; s < S_DIM; s++) {
            dots[s] += __shfl_xor_sync(0xffffffffu, dots[s], o);
            e2s[s]  += __shfl_xor_sync(0xffffffffu, e2s[s], o);
        }
    }
    if (lid == 0) {
        red_o[wid] = o2;
        #pragma unroll
        for (int s = 0; s < S_DIM; s++) {
            red_d[s][wid] = dots[s];
            red_e[s][wid] = e2s[s];
        }
    }
    __syncthreads();

    if (tid < S_DIM) {
        float d = 0.f, q = 0.f, oo = 0.f;
        #pragma unroll
        for (int w = 0; w < 16; w++) {
            d += red_d[tid][w];
            q += red_e[tid][w];
            oo += red_o[w];
        }
        const float denom = fmaxf(sqrtf(q) * sqrtf(oo), EPS);
        sh_sims[tid] = (d / denom) * (1.0f / S_DIM);
    }
    __syncthreads();

    float w[S_DIM];
    #pragma unroll
    for (int s = 0; s < S_DIM; s++) w[s] = sh_sims[s];

    float4 acc = make_float4(0.f, 0.f, 0.f, 0.f);
    #pragma unroll
    for (int s = 0; s < S_DIM; s++) {
        float4 v = se[s * (H_DIM / 4) + tid];
        acc.x += v.x * w[s]; acc.y += v.y * w[s];
        acc.z += v.z * w[s]; acc.w += v.w * w[s];
    }
    uint32_t h0, l0, h1, l1;
    split2(acc.x, acc.y, h0, l0);
    split2(acc.z, acc.w, h1, l1);
    const size_t o = (size_t)b * H_DIM + (size_t)tid * 4;
    *reinterpret_cast<uint2*>(g_Ahi + o) = make_uint2(h0, h1);
    *reinterpret_cast<uint2*>(g_Alo + o) = make_uint2(l0, l1);
}

// ---------------------------------------------------------------------------
// Kernel 2: HMMA GEMM  out = wr @ W^T + b   (3-product bf16 split, fp32 accum)
// A (hi/lo bf16) via 4-stage cp.async; B = W fp32 via register prefetch,
// converted to bf16 hi/lo in-kernel (double-buffered smem).
// Fragment double-buffering over ks hides LDSM latency under MMAs.
// ---------------------------------------------------------------------------
#define MT 128
#define NT 64
#define KT 64
#define NKC (H_DIM / KT)        // 32
#define LDS 144                 // bytes per smem row (72 bf16)
#define OFF_ALO (MT * LDS)                  // 18432
#define ASTAGE  (2 * MT * LDS)              // 36864
#define BBASE   (4 * ASTAGE)                // 147456
#define BSTAGE  (2 * NT * LDS)              // 18432 (hi + lo)
#define OFF_BLO (NT * LDS)                  // 9216
#define SM_GEMM (BBASE + 2 * BSTAGE)        // 184320

__global__ void __launch_bounds__(256, 1)
gemm_hmma(const float* __restrict__ Wm, const float* __restrict__ bias,
          float* __restrict__ out) {
    extern __shared__ __align__(16) char sm[];
    const uint32_t sbase = smem_u32(sm);
    const int tid = threadIdx.x;
    const int wid = tid >> 5;
    const int l   = tid & 31;
    const int bn = blockIdx.x;          // N tile (32)
    const int bm = blockIdx.y;          // M tile (4)

    const __nv_bfloat16* gAhi = g_Ahi + (size_t)bm * MT * H_DIM;
    const __nv_bfloat16* gAlo = g_Alo + (size_t)bm * MT * H_DIM;

    const int lrow = tid >> 3;          // 0..31
    const int lchk = tid & 7;           // 0..7

    auto load_stageA = [&](int buf, int kb) {
        const uint32_t sb = sbase + buf * ASTAGE;
        const int koff = kb * KT + lchk * 8;
        #pragma unroll
        for (int rr = 0; rr < 4; rr++) {
            const int row = rr * 32 + lrow;
            const uint32_t d = sb + row * LDS + lchk * 16;
            cpa16(d, gAhi + (size_t)row * H_DIM + koff);
            cpa16(d + OFF_ALO, gAlo + (size_t)row * H_DIM + koff);
        }
    };

    const int brow = tid >> 2;          // 0..63
    const int bq   = (tid & 3) * 16;    // col base
    const float* wrow = Wm + (size_t)(bn * NT + brow) * H_DIM + bq;

    float4 breg[4];
    auto ldg_B = [&](int kb) {
        const float* p = wrow + kb * KT;
        #pragma unroll
        for (int f = 0; f < 4; f++)
            breg[f] = *reinterpret_cast<const float4*>(p + f * 4);
    };
    auto sts_B = [&](int buf) {
        const uint32_t bb = BBASE + buf * BSTAGE + brow * LDS + bq * 2;
        #pragma unroll
        for (int f = 0; f < 4; f++) {
            uint32_t h0, l0, h1, l1;
            split2(breg[f].x, breg[f].y, h0, l0);
            split2(breg[f].z, breg[f].w, h1, l1);
            *reinterpret_cast<uint2*>(sm + bb + f * 8) = make_uint2(h0, h1);
            *reinterpret_cast<uint2*>(sm + bb + f * 8 + OFF_BLO) = make_uint2(l0, l1);
        }
    };

    // prologue: A stages 0,1,2 in flight; B(0) in smem, B(1) in regs
    ldg_B(0);
    load_stageA(0, 0); CP_COMMIT();
    load_stageA(1, 1); CP_COMMIT();
    load_stageA(2, 2); CP_COMMIT();
    sts_B(0);
    ldg_B(1);

    const int m0 = (wid & 3) * 32;
    const int n0 = (wid >> 2) * 32;

    const uint32_t aoff = (uint32_t)(((l & 7) + ((l >> 3) & 1) * 8) * LDS
                                     + ((l >> 4) & 1) * 16);
    const uint32_t boff = (uint32_t)(((l & 7) + ((l >> 4) & 1) * 8) * LDS
                                     + ((l >> 3) & 1) * 16);

    float acc[2][4][4];
    #pragma unroll
    for (int mi = 0; mi < 2; mi++)
        #pragma unroll
        for (int nj = 0; nj < 4; nj++)
            #pragma unroll
            for (int q = 0; q < 4; q++) acc[mi][nj][q] = 0.f;

    // double-buffered fragments
    uint32_t ah[2][2][4], al[2][2][4], bh[2][2][4], bl[2][2][4];

    for (int kc = 0; kc < NKC; kc++) {
        CP_WAIT2();                       // A stage kc resident
        __syncthreads();                  // B buffer (kc&1) published, old bufs free

        const uint32_t sa = sbase + (kc & 3) * ASTAGE;
        const uint32_t sb = sbase + BBASE + (kc & 1) * BSTAGE;
        const uint32_t aHiB = sa + m0 * LDS + aoff;
        const uint32_t aLoB = sa + OFF_ALO + m0 * LDS + aoff;
        const uint32_t bHiB = sb + n0 * LDS + boff;
        const uint32_t bLoB = sb + OFF_BLO + n0 * LDS + boff;

        // kick off fragment loads for ks=0 first (latency overlaps the LDG/STS)
        #pragma unroll
        for (int mi = 0; mi < 2; mi++) {
            ldsm4(ah[0][mi], aHiB + mi * 16 * LDS);
            ldsm4(al[0][mi], aLoB + mi * 16 * LDS);
        }
        #pragma unroll
        for (int ng = 0; ng < 2; ng++) {
            ldsm4(bh[0][ng], bHiB + ng * 16 * LDS);
            ldsm4(bl[0][ng], bLoB + ng * 16 * LDS);
        }

        if (kc + 1 < NKC) sts_B((kc + 1) & 1);
        if (kc + 3 < NKC) load_stageA((kc + 3) & 3, kc + 3);
        CP_COMMIT();
        if (kc + 2 < NKC) ldg_B(kc + 2);

        #pragma unroll
        for (int ks = 0; ks < 4; ks++) {
            const int cur = ks & 1, nxt = cur ^ 1;
            if (ks < 3) {                 // prefetch fragments for ks+1
                #pragma unroll
                for (int mi = 0; mi < 2; mi++) {
                    ldsm4(ah[nxt][mi], aHiB + mi * 16 * LDS + (ks + 1) * 32);
                    ldsm4(al[nxt][mi], aLoB + mi * 16 * LDS + (ks + 1) * 32);
                }
                #pragma unroll
                for (int ng = 0; ng < 2; ng++) {
                    ldsm4(bh[nxt][ng], bHiB + ng * 16 * LDS + (ks + 1) * 32);
                    ldsm4(bl[nxt][ng], bLoB + ng * 16 * LDS + (ks + 1) * 32);
                }
            }
            #pragma unroll
            for (int mi = 0; mi < 2; mi++) {
                #pragma unroll
                for (int nj = 0; nj < 4; nj++) {
                    const int ng = nj >> 1, sp = (nj & 1) * 2;
                    mma16816(acc[mi][nj], ah[cur][mi], bh[cur][ng][sp], bh[cur][ng][sp + 1]);
                    mma16816(acc[mi][nj], ah[cur][mi], bl[cur][ng][sp], bl[cur][ng][sp + 1]);
                    mma16816(acc[mi][nj], al[cur][mi], bh[cur][ng][sp], bh[cur][ng][sp + 1]);
                }
            }
        }
    }

    // epilogue
    #pragma unroll
    for (int mi = 0; mi < 2; mi++) {
        const int row = bm * MT + m0 + mi * 16 + (l >> 2);
        #pragma unroll
        for (int nj = 0; nj < 4; nj++) {
            const int gcol = bn * NT + n0 + nj * 8 + (l & 3) * 2;
            const float b0 = bias[gcol], b1 = bias[gcol + 1];
            float2 v0 = make_float2(acc[mi][nj][0] + b0, acc[mi][nj][1] + b1);
            float2 v1 = make_float2(acc[mi][nj][2] + b0, acc[mi][nj][3] + b1);
            *reinterpret_cast<float2*>(out + (size_t)row * H_DIM + gcol) = v0;
            *reinterpret_cast<float2*>(out + (size_t)(row + 8) * H_DIM + gcol) = v1;
        }
    }
}

// ---------------------------------------------------------------------------
extern "C" void kernel_launch(void* const* d_in, const int* in_sizes, int n_in,
                              void* d_out, int out_size) {
    const float* og   = (const float*)d_in[0];   // (B, H)
    const float* enh  = (const float*)d_in[1];   // (S, B, H)
    const float* Wm   = (const float*)d_in[2];   // (H, H)
    const float* bias = (const float*)d_in[3];   // (H,)
    float* out = (float*)d_out;                  // (B, H)

    cudaFuncSetAttribute(gemm_hmma, cudaFuncAttributeMaxDynamicSharedMemorySize,
                         SM_GEMM);
    cudaFuncSetAttribute(fused_prep, cudaFuncAttributeMaxDynamicSharedMemorySize,
                         FUSED_SMEM);

    fused_prep<<<B_DIM, 512, FUSED_SMEM>>>(og, enh);
    gemm_hmma<<<dim3(H_DIM / NT, B_DIM / MT), 256, SM_GEMM>>>(Wm, bias, out);
}